// round 1
// baseline (speedup 1.0000x reference)
#include <cuda_runtime.h>
#include <math.h>

#define EPSF 1e-9f
#define MAXF 4096
#define MAXB 8
#define FCHUNK 768   // faces resident in smem per chunk

// Per-face affine coefficients (precomputed):
//   w1(px,py) = A1*px + B1*py + C1
//   w2(px,py) = A2*px + B2*py + C2
//   invz(px,py) = Az*px + Bz*py + Cz
// fa = (A1,B1,C1,A2), fb = (B2,C2,Az,Bz), fc = (Cz, 1/z0, 1/z1, 1/z2)
// C1 is NaN-poisoned when face is invalid (|den|<=1e-8) or not front-facing.
__device__ float4 g_fa[MAXB * MAXF];
__device__ float4 g_fb[MAXB * MAXF];
__device__ float4 g_fc[MAXB * MAXF];
__device__ float4 g_tex4[MAXF * 6];       // tanh(textures), 24 floats/face
__device__ float  g_part[8192];           // per-block partial sums

__global__ void prep_kernel(const float* __restrict__ verts,
                            const int*   __restrict__ faces,
                            const float* __restrict__ Kmat,
                            const float* __restrict__ Rmat,
                            const float* __restrict__ tvec,
                            const float* __restrict__ textures,
                            int B, int V, int F, int S) {
    int idx = blockIdx.x * blockDim.x + threadIdx.x;
    int stride = gridDim.x * blockDim.x;

    // tex = tanh(textures[0]), (F,2,2,2,3) -> F*24 floats
    int texN = F * 24;
    for (int i = idx; i < texN; i += stride)
        ((float*)g_tex4)[i] = tanhf(textures[i]);

    if (idx >= B * F) return;
    int b = idx / F;
    int f = idx - b * F;

    const float* Rb = Rmat + b * 9;
    const float* Kb = Kmat + b * 9;
    const float* tb = tvec + b * 3;

    float xs[3], ys[3], zs[3];
#pragma unroll
    for (int vi = 0; vi < 3; vi++) {
        int vid = faces[(b * F + f) * 3 + vi];
        const float* p = verts + ((size_t)b * V + vid) * 3;
        float px = p[0], py = p[1], pz = p[2];
        float vx = Rb[0] * px + Rb[1] * py + Rb[2] * pz + tb[0];
        float vy = Rb[3] * px + Rb[4] * py + Rb[5] * pz + tb[1];
        float vz = Rb[6] * px + Rb[7] * py + Rb[8] * pz + tb[2];
        float xh = vx / (vz + EPSF);
        float yh = vy / (vz + EPSF);
        float u  = Kb[0] * xh + Kb[1] * yh + Kb[2];
        float pv = Kb[3] * xh + Kb[4] * yh + Kb[5];
        float v  = (float)S - pv;
        u = 2.0f * (u - 0.5f * (float)S) / (float)S;
        v = 2.0f * (v - 0.5f * (float)S) / (float)S;
        xs[vi] = u; ys[vi] = v; zs[vi] = vz;
    }

    float e1x = xs[1] - xs[0], e1y = ys[1] - ys[0];
    float e2x = xs[2] - xs[0], e2y = ys[2] - ys[0];
    float den = e1x * e2y - e2x * e1y;
    bool valid = fabsf(den) > 1e-8f;
    float dens = valid ? den : 1.0f;
    bool front = fminf(zs[0], fminf(zs[1], zs[2])) > EPSF;
    float rden = 1.0f / dens;

    float A1 =  e2y * rden;
    float B1 = -e2x * rden;
    float C1 = (ys[0] * e2x - xs[0] * e2y) * rden;
    float A2 = -e1y * rden;
    float B2 =  e1x * rden;
    float C2 = (xs[0] * e1y - ys[0] * e1x) * rden;

    float iz0 = 1.0f / zs[0], iz1 = 1.0f / zs[1], iz2 = 1.0f / zs[2];
    float d1 = iz1 - iz0, d2 = iz2 - iz0;
    float Az = A1 * d1 + A2 * d2;
    float Bz = B1 * d1 + B2 * d2;
    float Cz = iz0 + C1 * d1 + C2 * d2;

    if (!(valid && front)) C1 = __int_as_float(0x7FC00000);  // NaN -> never inside

    g_fa[idx] = make_float4(A1, B1, C1, A2);
    g_fb[idx] = make_float4(B2, C2, Az, Bz);
    g_fc[idx] = make_float4(Cz, iz0, iz1, iz2);
}

// block (64,4) = 256 threads; each thread covers 4 consecutive x pixels.
__global__ void raster_kernel(const float* __restrict__ image_ref,
                              int B, int F, int S) {
    __shared__ float4 sa[FCHUNK];
    __shared__ float4 sb[FCHUNK];
    __shared__ float  scz[FCHUNK];
    __shared__ float  sred[256];

    const int b   = blockIdx.z;
    const int tid = threadIdx.y * 64 + threadIdx.x;
    const int y   = blockIdx.y * 4 + threadIdx.y;
    const int x0  = (blockIdx.x * 64 + threadIdx.x) * 4;
    const float invS = 1.0f / (float)S;
    const float step = 2.0f * invS;
    const float py  = (2.0f * (float)y  + 1.0f - (float)S) * invS;
    const float px0 = (2.0f * (float)x0 + 1.0f - (float)S) * invS;
    const bool active = (y < S) && (x0 + 3 < S);

    float best_iv[4];
    int   best_f[4];
#pragma unroll
    for (int p = 0; p < 4; p++) { best_iv[p] = EPSF; best_f[p] = -1; }

    const float4* fa_g = g_fa + (size_t)b * F;
    const float4* fb_g = g_fb + (size_t)b * F;
    const float4* fc_g = g_fc + (size_t)b * F;

    for (int f0 = 0; f0 < F; f0 += FCHUNK) {
        int nf = min(FCHUNK, F - f0);
        for (int i = tid; i < nf; i += 256) {
            sa[i]  = fa_g[f0 + i];
            sb[i]  = fb_g[f0 + i];
            scz[i] = fc_g[f0 + i].x;
        }
        __syncthreads();

        if (active) {
            for (int f = 0; f < nf; f++) {
                const float4 fa = sa[f];
                const float4 fb = sb[f];
                const float  cz = scz[f];
                // base-pixel values
                const float w1b = fmaf(fa.x, px0, fmaf(fa.y, py, fa.z));
                const float w2b = fmaf(fa.w, px0, fmaf(fb.x, py, fb.y));
                const float ivb = fmaf(fb.z, px0, fmaf(fb.w, py, cz));
#pragma unroll
                for (int p = 0; p < 4; p++) {
                    const float ps = (float)p * step;
                    float w1 = fmaf(fa.x, ps, w1b);
                    float w2 = fmaf(fa.w, ps, w2b);
                    float iv = fmaf(fb.z, ps, ivb);
                    float w0 = 1.0f - w1 - w2;
                    // inside & invz>EPS & strictly-better depth (argmax invz,
                    // first index wins ties). NaN C1 => comparisons false.
                    if (w0 >= 0.0f && w1 >= 0.0f && w2 >= 0.0f && iv > best_iv[p]) {
                        best_iv[p] = iv;
                        best_f[p]  = f0 + f;
                    }
                }
            }
        }
        __syncthreads();
    }

    // Second pass: perspective-correct trilinear texture for winning face,
    // squared error vs reference image.
    float lsum = 0.0f;
    if (active) {
        float colv[4][3];
#pragma unroll
        for (int p = 0; p < 4; p++) {
            float c0 = 0.0f, c1 = 0.0f, c2 = 0.0f;
            int f = best_f[p];
            if (f >= 0) {
                const float4 fa = fa_g[f];
                const float4 fb = fb_g[f];
                const float4 fc = fc_g[f];
                const float px = px0 + (float)p * step;
                float w1 = fmaf(fa.x, px, fmaf(fa.y, py, fa.z));
                float w2 = fmaf(fa.w, px, fmaf(fb.x, py, fb.y));
                float iv = fmaf(fb.z, px, fmaf(fb.w, py, fc.x));
                float w0 = 1.0f - w1 - w2;
                float iz = fmaxf(iv, EPSF);
                float r  = 1.0f / iz;
                float wp0 = __saturatef(w0 * fc.y * r);
                float wp1 = __saturatef(w1 * fc.z * r);
                float wp2 = __saturatef(w2 * fc.w * r);
                float q0 = 1.0f - wp0, q1 = 1.0f - wp1, q2 = 1.0f - wp2;
                float wA = q0 * q1, wB = q0 * wp1, wC = wp0 * q1, wD = wp0 * wp1;
                float w000 = wA * q2, w001 = wA * wp2;
                float w010 = wB * q2, w011 = wB * wp2;
                float w100 = wC * q2, w101 = wC * wp2;
                float w110 = wD * q2, w111 = wD * wp2;

                float tv[24];
#pragma unroll
                for (int q = 0; q < 6; q++) {
                    float4 v = g_tex4[f * 6 + q];
                    tv[q * 4 + 0] = v.x; tv[q * 4 + 1] = v.y;
                    tv[q * 4 + 2] = v.z; tv[q * 4 + 3] = v.w;
                }
#pragma unroll
                for (int c = 0; c < 3; c++) {
                    float col = w000 * tv[0 + c]  + w001 * tv[3 + c]
                              + w010 * tv[6 + c]  + w011 * tv[9 + c]
                              + w100 * tv[12 + c] + w101 * tv[15 + c]
                              + w110 * tv[18 + c] + w111 * tv[21 + c];
                    if (c == 0) c0 = col; else if (c == 1) c1 = col; else c2 = col;
                }
            }
            colv[p][0] = c0; colv[p][1] = c1; colv[p][2] = c2;
        }
#pragma unroll
        for (int c = 0; c < 3; c++) {
            const float4 rv = *(const float4*)(image_ref +
                ((size_t)(b * 3 + c) * S + y) * S + x0);
            float d0 = colv[0][c] - rv.x;
            float d1 = colv[1][c] - rv.y;
            float d2 = colv[2][c] - rv.z;
            float d3 = colv[3][c] - rv.w;
            lsum += d0 * d0 + d1 * d1 + d2 * d2 + d3 * d3;
        }
    }

    sred[tid] = lsum;
    __syncthreads();
#pragma unroll
    for (int s = 128; s > 0; s >>= 1) {
        if (tid < s) sred[tid] += sred[tid + s];
        __syncthreads();
    }
    if (tid == 0)
        g_part[(size_t)blockIdx.z * gridDim.x * gridDim.y
               + blockIdx.y * gridDim.x + blockIdx.x] = sred[0];
}

__global__ void reduce_kernel(float* __restrict__ out, int nb) {
    __shared__ float sred[256];
    float s = 0.0f;
    for (int i = threadIdx.x; i < nb; i += 256) s += g_part[i];
    sred[threadIdx.x] = s;
    __syncthreads();
#pragma unroll
    for (int k = 128; k > 0; k >>= 1) {
        if (threadIdx.x < k) sred[threadIdx.x] += sred[threadIdx.x + k];
        __syncthreads();
    }
    if (threadIdx.x == 0) out[0] = sred[0];
}

extern "C" void kernel_launch(void* const* d_in, const int* in_sizes, int n_in,
                              void* d_out, int out_size) {
    const float* vertices  = (const float*)d_in[0];
    const int*   faces     = (const int*)  d_in[1];
    const float* Kmat      = (const float*)d_in[2];
    const float* Rmat      = (const float*)d_in[3];
    const float* tvec      = (const float*)d_in[4];
    const float* textures  = (const float*)d_in[5];
    const float* image_ref = (const float*)d_in[6];

    int B = in_sizes[2] / 9;                 // K is (B,3,3)
    int V = in_sizes[0] / (3 * B);
    int F = in_sizes[1] / (3 * B);
    int ss = in_sizes[6] / (3 * B);          // S*S
    int S = (int)(sqrt((double)ss) + 0.5);

    float* out = (float*)d_out;

    int prepN = (B * F > F * 24) ? B * F : F * 24;
    prep_kernel<<<(prepN + 255) / 256, 256>>>(vertices, faces, Kmat, Rmat,
                                              tvec, textures, B, V, F, S);

    dim3 blk(64, 4);
    dim3 grd((S + 255) / 256, (S + 3) / 4, B);
    raster_kernel<<<grd, blk>>>(image_ref, B, F, S);

    int nb = grd.x * grd.y * grd.z;
    reduce_kernel<<<1, 256>>>(out, nb);
}

// round 2
// speedup vs baseline: 1.0971x; 1.0971x over previous
#include <cuda_runtime.h>
#include <math.h>

#define EPSF 1e-9f
#define MAXF 4096
#define MAXB 8
#define FCHUNK 1024   // faces compacted per chunk (smem cap)

// Per-face affine coefficients (precomputed):
//   w1(px,py) = A1*px + B1*py + C1
//   w2(px,py) = A2*px + B2*py + C2
//   invz(px,py) = Az*px + Bz*py + Cz
// fa = (A1,B1,C1,A2), fb = (B2,C2,Az,Bz), fc = (Cz, 1/z0, 1/z1, 1/z2)
// bb = (xmin, xmax, ymin, ymax) in NDC; empty sentinel if invalid/backface.
// C1 is NaN-poisoned when face is invalid so it can never win even if listed.
__device__ float4 g_fa[MAXB * MAXF];
__device__ float4 g_fb[MAXB * MAXF];
__device__ float4 g_fc[MAXB * MAXF];
__device__ float4 g_bb[MAXB * MAXF];
__device__ float4 g_tex4[MAXF * 6];       // tanh(textures), 24 floats/face
__device__ float  g_part[8192];           // per-block partial sums

__global__ void prep_kernel(const float* __restrict__ verts,
                            const int*   __restrict__ faces,
                            const float* __restrict__ Kmat,
                            const float* __restrict__ Rmat,
                            const float* __restrict__ tvec,
                            const float* __restrict__ textures,
                            int B, int V, int F, int S) {
    int idx = blockIdx.x * blockDim.x + threadIdx.x;
    int stride = gridDim.x * blockDim.x;

    // tex = tanh(textures[0]), vectorized: F*6 float4s
    int texN4 = F * 6;
    const float4* t4 = (const float4*)textures;
    for (int i = idx; i < texN4; i += stride) {
        float4 v = t4[i];
        g_tex4[i] = make_float4(tanhf(v.x), tanhf(v.y), tanhf(v.z), tanhf(v.w));
    }

    if (idx >= B * F) return;
    int b = idx / F;
    int f = idx - b * F;

    const float* Rb = Rmat + b * 9;
    const float* Kb = Kmat + b * 9;
    const float* tb = tvec + b * 3;

    float xs[3], ys[3], zs[3];
#pragma unroll
    for (int vi = 0; vi < 3; vi++) {
        int vid = faces[(b * F + f) * 3 + vi];
        const float* p = verts + ((size_t)b * V + vid) * 3;
        float px = p[0], py = p[1], pz = p[2];
        float vx = Rb[0] * px + Rb[1] * py + Rb[2] * pz + tb[0];
        float vy = Rb[3] * px + Rb[4] * py + Rb[5] * pz + tb[1];
        float vz = Rb[6] * px + Rb[7] * py + Rb[8] * pz + tb[2];
        float xh = vx / (vz + EPSF);
        float yh = vy / (vz + EPSF);
        float u  = Kb[0] * xh + Kb[1] * yh + Kb[2];
        float pv = Kb[3] * xh + Kb[4] * yh + Kb[5];
        float v  = (float)S - pv;
        u = 2.0f * (u - 0.5f * (float)S) / (float)S;
        v = 2.0f * (v - 0.5f * (float)S) / (float)S;
        xs[vi] = u; ys[vi] = v; zs[vi] = vz;
    }

    float e1x = xs[1] - xs[0], e1y = ys[1] - ys[0];
    float e2x = xs[2] - xs[0], e2y = ys[2] - ys[0];
    float den = e1x * e2y - e2x * e1y;
    bool valid = fabsf(den) > 1e-8f;
    float dens = valid ? den : 1.0f;
    bool front = fminf(zs[0], fminf(zs[1], zs[2])) > EPSF;
    float rden = 1.0f / dens;

    float A1 =  e2y * rden;
    float B1 = -e2x * rden;
    float C1 = (ys[0] * e2x - xs[0] * e2y) * rden;
    float A2 = -e1y * rden;
    float B2 =  e1x * rden;
    float C2 = (xs[0] * e1y - ys[0] * e1x) * rden;

    float iz0 = 1.0f / zs[0], iz1 = 1.0f / zs[1], iz2 = 1.0f / zs[2];
    float d1 = iz1 - iz0, d2 = iz2 - iz0;
    float Az = A1 * d1 + A2 * d2;
    float Bz = B1 * d1 + B2 * d2;
    float Cz = iz0 + C1 * d1 + C2 * d2;

    float xmin = fminf(xs[0], fminf(xs[1], xs[2]));
    float xmax = fmaxf(xs[0], fmaxf(xs[1], xs[2]));
    float ymin = fminf(ys[0], fminf(ys[1], ys[2]));
    float ymax = fmaxf(ys[0], fmaxf(ys[1], ys[2]));

    if (!(valid && front)) {
        C1 = __int_as_float(0x7FC00000);       // NaN -> never inside
        xmin = 3.0e9f; xmax = -3.0e9f;         // empty bbox -> never listed
        ymin = 3.0e9f; ymax = -3.0e9f;
    }

    g_fa[idx] = make_float4(A1, B1, C1, A2);
    g_fb[idx] = make_float4(B2, C2, Az, Bz);
    g_fc[idx] = make_float4(Cz, iz0, iz1, iz2);
    g_bb[idx] = make_float4(xmin, xmax, ymin, ymax);
}

// block (4,16) = 64 threads; tile = 16x16 pixels; 4 px per thread in x.
__global__ void raster_kernel(const float* __restrict__ image_ref,
                              int B, int F, int S) {
    __shared__ int    slist[FCHUNK];
    __shared__ float4 sa[FCHUNK];
    __shared__ float4 sb[FCHUNK];
    __shared__ float  scz[FCHUNK];
    __shared__ int    scount;
    __shared__ float  swred[2];

    const int b   = blockIdx.z;
    const int tid = threadIdx.y * 4 + threadIdx.x;
    const int y   = blockIdx.y * 16 + threadIdx.y;
    const int x0  = (blockIdx.x * 4 + threadIdx.x) * 4;
    const float invS = 1.0f / (float)S;
    const float step = 2.0f * invS;
    const float py  = (2.0f * (float)y  + 1.0f - (float)S) * invS;
    const float px0 = (2.0f * (float)x0 + 1.0f - (float)S) * invS;
    const bool active = (y < S) && (x0 + 3 < S);

    // tile NDC bounds (pixel centers)
    const int tpx0 = blockIdx.x * 16, tpy0 = blockIdx.y * 16;
    const float tx0 = (2.0f * (float)tpx0 + 1.0f - (float)S) * invS;
    const float tx1 = (2.0f * (float)(tpx0 + 15) + 1.0f - (float)S) * invS;
    const float ty0 = (2.0f * (float)tpy0 + 1.0f - (float)S) * invS;
    const float ty1 = (2.0f * (float)(tpy0 + 15) + 1.0f - (float)S) * invS;

    float best_iv[4];
    int   best_i[4];
#pragma unroll
    for (int p = 0; p < 4; p++) { best_iv[p] = EPSF; best_i[p] = -1; }

    const float4* fa_g = g_fa + (size_t)b * F;
    const float4* fb_g = g_fb + (size_t)b * F;
    const float4* fc_g = g_fc + (size_t)b * F;
    const float4* bb_g = g_bb + (size_t)b * F;

    int best_face[4];
#pragma unroll
    for (int p = 0; p < 4; p++) best_face[p] = -1;

    for (int f0 = 0; f0 < F; f0 += FCHUNK) {
        int chunk = min(FCHUNK, F - f0);

        // ordered compaction by warp 0 (preserves ascending face order)
        if (tid < 32) {
            int cnt = 0;
            for (int base = 0; base < chunk; base += 32) {
                int f = base + tid;
                bool ok = false;
                if (f < chunk) {
                    float4 bb = bb_g[f0 + f];
                    ok = (bb.x <= tx1) && (bb.y >= tx0) &&
                         (bb.z <= ty1) && (bb.w >= ty0);
                }
                unsigned m = __ballot_sync(0xffffffffu, ok);
                if (ok)
                    slist[cnt + __popc(m & ((1u << tid) - 1u))] = f0 + f;
                cnt += __popc(m);
            }
            if (tid == 0) scount = cnt;
        }
        __syncthreads();
        const int nf = scount;

        // gather listed faces into smem
        for (int i = tid; i < nf; i += 64) {
            int f = slist[i];
            sa[i]  = fa_g[f];
            sb[i]  = fb_g[f];
            scz[i] = fc_g[f].x;
        }
        __syncthreads();

        if (active) {
            for (int i = 0; i < nf; i++) {
                const float4 fa = sa[i];
                const float4 fb = sb[i];
                const float  cz = scz[i];
                const float w1b = fmaf(fa.x, px0, fmaf(fa.y, py, fa.z));
                const float w2b = fmaf(fa.w, px0, fmaf(fb.x, py, fb.y));
                const float ivb = fmaf(fb.z, px0, fmaf(fb.w, py, cz));
#pragma unroll
                for (int p = 0; p < 4; p++) {
                    const float ps = (float)p * step;
                    float w1 = fmaf(fa.x, ps, w1b);
                    float w2 = fmaf(fa.w, ps, w2b);
                    float iv = fmaf(fb.z, ps, ivb);
                    float w0 = 1.0f - w1 - w2;
                    if (w0 >= 0.0f && w1 >= 0.0f && w2 >= 0.0f && iv > best_iv[p]) {
                        best_iv[p] = iv;
                        best_i[p]  = i;
                    }
                }
            }
            // map local winners to face ids before slist is overwritten
#pragma unroll
            for (int p = 0; p < 4; p++)
                if (best_i[p] >= 0) { best_face[p] = slist[best_i[p]]; best_i[p] = -1; }
        }
        __syncthreads();
    }

    // Second pass: perspective-correct trilinear texture + squared error.
    float lsum = 0.0f;
    if (active) {
        float colv[4][3];
#pragma unroll
        for (int p = 0; p < 4; p++) {
            float c0 = 0.0f, c1 = 0.0f, c2 = 0.0f;
            int f = best_face[p];
            if (f >= 0) {
                const float4 fa = fa_g[f];
                const float4 fb = fb_g[f];
                const float4 fc = fc_g[f];
                const float px = px0 + (float)p * step;
                float w1 = fmaf(fa.x, px, fmaf(fa.y, py, fa.z));
                float w2 = fmaf(fa.w, px, fmaf(fb.x, py, fb.y));
                float iv = fmaf(fb.z, px, fmaf(fb.w, py, fc.x));
                float w0 = 1.0f - w1 - w2;
                float iz = fmaxf(iv, EPSF);
                float r  = 1.0f / iz;
                float wp0 = __saturatef(w0 * fc.y * r);
                float wp1 = __saturatef(w1 * fc.z * r);
                float wp2 = __saturatef(w2 * fc.w * r);
                float q0 = 1.0f - wp0, q1 = 1.0f - wp1, q2 = 1.0f - wp2;
                float wA = q0 * q1, wB = q0 * wp1, wC = wp0 * q1, wD = wp0 * wp1;
                float w000 = wA * q2, w001 = wA * wp2;
                float w010 = wB * q2, w011 = wB * wp2;
                float w100 = wC * q2, w101 = wC * wp2;
                float w110 = wD * q2, w111 = wD * wp2;

                float tv[24];
#pragma unroll
                for (int q = 0; q < 6; q++) {
                    float4 v = g_tex4[f * 6 + q];
                    tv[q * 4 + 0] = v.x; tv[q * 4 + 1] = v.y;
                    tv[q * 4 + 2] = v.z; tv[q * 4 + 3] = v.w;
                }
#pragma unroll
                for (int c = 0; c < 3; c++) {
                    float col = w000 * tv[0 + c]  + w001 * tv[3 + c]
                              + w010 * tv[6 + c]  + w011 * tv[9 + c]
                              + w100 * tv[12 + c] + w101 * tv[15 + c]
                              + w110 * tv[18 + c] + w111 * tv[21 + c];
                    if (c == 0) c0 = col; else if (c == 1) c1 = col; else c2 = col;
                }
            }
            colv[p][0] = c0; colv[p][1] = c1; colv[p][2] = c2;
        }
#pragma unroll
        for (int c = 0; c < 3; c++) {
            const float4 rv = *(const float4*)(image_ref +
                ((size_t)(b * 3 + c) * S + y) * S + x0);
            float d0 = colv[0][c] - rv.x;
            float d1 = colv[1][c] - rv.y;
            float d2 = colv[2][c] - rv.z;
            float d3 = colv[3][c] - rv.w;
            lsum += d0 * d0 + d1 * d1 + d2 * d2 + d3 * d3;
        }
    }

    // deterministic block reduction (2 warps)
#pragma unroll
    for (int o = 16; o > 0; o >>= 1)
        lsum += __shfl_down_sync(0xffffffffu, lsum, o);
    if ((tid & 31) == 0) swred[tid >> 5] = lsum;
    __syncthreads();
    if (tid == 0)
        g_part[(size_t)blockIdx.z * gridDim.x * gridDim.y
               + blockIdx.y * gridDim.x + blockIdx.x] = swred[0] + swred[1];
}

__global__ void reduce_kernel(float* __restrict__ out, int nb) {
    __shared__ float sred[256];
    float s = 0.0f;
    for (int i = threadIdx.x; i < nb; i += 256) s += g_part[i];
    sred[threadIdx.x] = s;
    __syncthreads();
#pragma unroll
    for (int k = 128; k > 0; k >>= 1) {
        if (threadIdx.x < k) sred[threadIdx.x] += sred[threadIdx.x + k];
        __syncthreads();
    }
    if (threadIdx.x == 0) out[0] = sred[0];
}

extern "C" void kernel_launch(void* const* d_in, const int* in_sizes, int n_in,
                              void* d_out, int out_size) {
    const float* vertices  = (const float*)d_in[0];
    const int*   faces     = (const int*)  d_in[1];
    const float* Kmat      = (const float*)d_in[2];
    const float* Rmat      = (const float*)d_in[3];
    const float* tvec      = (const float*)d_in[4];
    const float* textures  = (const float*)d_in[5];
    const float* image_ref = (const float*)d_in[6];

    int B = in_sizes[2] / 9;                 // K is (B,3,3)
    int V = in_sizes[0] / (3 * B);
    int F = in_sizes[1] / (3 * B);
    int ss = in_sizes[6] / (3 * B);          // S*S
    int S = (int)(sqrt((double)ss) + 0.5);

    float* out = (float*)d_out;

    int prepN = (B * F > F * 6) ? B * F : F * 6;
    prep_kernel<<<(prepN + 255) / 256, 256>>>(vertices, faces, Kmat, Rmat,
                                              tvec, textures, B, V, F, S);

    dim3 blk(4, 16);
    dim3 grd((S + 15) / 16, (S + 15) / 16, B);
    raster_kernel<<<grd, blk>>>(image_ref, B, F, S);

    int nb = grd.x * grd.y * grd.z;
    reduce_kernel<<<1, 256>>>(out, nb);
}

// round 3
// speedup vs baseline: 1.7143x; 1.5626x over previous
#include <cuda_runtime.h>
#include <math.h>

#define EPSF 1e-9f
#define MAXF 4096
#define MAXB 8
#define FCHUNK 1024   // faces compacted per chunk (smem cap)

// Per-face affine coefficients (precomputed):
//   w1(px,py) = A1*px + B1*py + C1
//   w2(px,py) = A2*px + B2*py + C2
//   invz(px,py) = Az*px + Bz*py + Cz
// fa = (A1,B1,C1,A2), fb = (B2,C2,Az,Bz), fc = (Cz, 1/z0, 1/z1, 1/z2)
// bb = (xmin, xmax, ymin, ymax) in NDC; empty sentinel if invalid/backface.
// C1 is NaN-poisoned when face is invalid so it can never win even if listed.
__device__ float4 g_fa[MAXB * MAXF];
__device__ float4 g_fb[MAXB * MAXF];
__device__ float4 g_fc[MAXB * MAXF];
__device__ float4 g_bb[MAXB * MAXF];
__device__ float4 g_tex4[MAXF * 6];       // tanh(textures), 24 floats/face
__device__ float  g_part[8192];           // per-block partial sums

__global__ void prep_kernel(const float* __restrict__ verts,
                            const int*   __restrict__ faces,
                            const float* __restrict__ Kmat,
                            const float* __restrict__ Rmat,
                            const float* __restrict__ tvec,
                            const float* __restrict__ textures,
                            int B, int V, int F, int S) {
    int idx = blockIdx.x * blockDim.x + threadIdx.x;
    int stride = gridDim.x * blockDim.x;

    // tex = tanh(textures[0]), vectorized: F*6 float4s
    int texN4 = F * 6;
    const float4* t4 = (const float4*)textures;
    for (int i = idx; i < texN4; i += stride) {
        float4 v = t4[i];
        g_tex4[i] = make_float4(tanhf(v.x), tanhf(v.y), tanhf(v.z), tanhf(v.w));
    }

    if (idx >= B * F) return;
    int b = idx / F;
    int f = idx - b * F;

    const float* Rb = Rmat + b * 9;
    const float* Kb = Kmat + b * 9;
    const float* tb = tvec + b * 3;

    float xs[3], ys[3], zs[3];
#pragma unroll
    for (int vi = 0; vi < 3; vi++) {
        int vid = faces[(b * F + f) * 3 + vi];
        const float* p = verts + ((size_t)b * V + vid) * 3;
        float px = p[0], py = p[1], pz = p[2];
        float vx = Rb[0] * px + Rb[1] * py + Rb[2] * pz + tb[0];
        float vy = Rb[3] * px + Rb[4] * py + Rb[5] * pz + tb[1];
        float vz = Rb[6] * px + Rb[7] * py + Rb[8] * pz + tb[2];
        float xh = vx / (vz + EPSF);
        float yh = vy / (vz + EPSF);
        float u  = Kb[0] * xh + Kb[1] * yh + Kb[2];
        float pv = Kb[3] * xh + Kb[4] * yh + Kb[5];
        float v  = (float)S - pv;
        u = 2.0f * (u - 0.5f * (float)S) / (float)S;
        v = 2.0f * (v - 0.5f * (float)S) / (float)S;
        xs[vi] = u; ys[vi] = v; zs[vi] = vz;
    }

    float e1x = xs[1] - xs[0], e1y = ys[1] - ys[0];
    float e2x = xs[2] - xs[0], e2y = ys[2] - ys[0];
    float den = e1x * e2y - e2x * e1y;
    bool valid = fabsf(den) > 1e-8f;
    float dens = valid ? den : 1.0f;
    bool front = fminf(zs[0], fminf(zs[1], zs[2])) > EPSF;
    float rden = 1.0f / dens;

    float A1 =  e2y * rden;
    float B1 = -e2x * rden;
    float C1 = (ys[0] * e2x - xs[0] * e2y) * rden;
    float A2 = -e1y * rden;
    float B2 =  e1x * rden;
    float C2 = (xs[0] * e1y - ys[0] * e1x) * rden;

    float iz0 = 1.0f / zs[0], iz1 = 1.0f / zs[1], iz2 = 1.0f / zs[2];
    float d1 = iz1 - iz0, d2 = iz2 - iz0;
    float Az = A1 * d1 + A2 * d2;
    float Bz = B1 * d1 + B2 * d2;
    float Cz = iz0 + C1 * d1 + C2 * d2;

    float xmin = fminf(xs[0], fminf(xs[1], xs[2]));
    float xmax = fmaxf(xs[0], fmaxf(xs[1], xs[2]));
    float ymin = fminf(ys[0], fminf(ys[1], ys[2]));
    float ymax = fmaxf(ys[0], fmaxf(ys[1], ys[2]));

    if (!(valid && front)) {
        C1 = __int_as_float(0x7FC00000);       // NaN -> never inside
        xmin = 3.0e9f; xmax = -3.0e9f;         // empty bbox -> never listed
        ymin = 3.0e9f; ymax = -3.0e9f;
    }

    g_fa[idx] = make_float4(A1, B1, C1, A2);
    g_fb[idx] = make_float4(B2, C2, Az, Bz);
    g_fc[idx] = make_float4(Cz, iz0, iz1, iz2);
    g_bb[idx] = make_float4(xmin, xmax, ymin, ymax);
}

// block (16,16) = 256 threads = 8 warps; tile = 16x16 pixels; 1 px/thread.
__global__ void raster_kernel(const float* __restrict__ image_ref,
                              int B, int F, int S) {
    __shared__ int    slist[FCHUNK];
    __shared__ float4 sa[FCHUNK];
    __shared__ float4 sb[FCHUNK];
    __shared__ float  scz[FCHUNK];
    __shared__ int    swcnt[8];
    __shared__ float  swred[8];

    const int b    = blockIdx.z;
    const int tid  = threadIdx.y * 16 + threadIdx.x;
    const int warp = tid >> 5;
    const int lane = tid & 31;
    const int x    = blockIdx.x * 16 + threadIdx.x;
    const int y    = blockIdx.y * 16 + threadIdx.y;
    const float invS = 1.0f / (float)S;
    const float py = (2.0f * (float)y + 1.0f - (float)S) * invS;
    const float px = (2.0f * (float)x + 1.0f - (float)S) * invS;
    const bool active = (x < S) && (y < S);

    // tile NDC bounds (pixel centers)
    const int tpx0 = blockIdx.x * 16, tpy0 = blockIdx.y * 16;
    const float tx0 = (2.0f * (float)tpx0 + 1.0f - (float)S) * invS;
    const float tx1 = (2.0f * (float)(tpx0 + 15) + 1.0f - (float)S) * invS;
    const float ty0 = (2.0f * (float)tpy0 + 1.0f - (float)S) * invS;
    const float ty1 = (2.0f * (float)(tpy0 + 15) + 1.0f - (float)S) * invS;

    const float4* fa_g = g_fa + (size_t)b * F;
    const float4* fb_g = g_fb + (size_t)b * F;
    const float4* fc_g = g_fc + (size_t)b * F;
    const float4* bb_g = g_bb + (size_t)b * F;

    float best_iv  = EPSF;
    int   best_face = -1;

    for (int f0 = 0; f0 < F; f0 += FCHUNK) {
        const int chunk = min(FCHUNK, F - f0);

        // ordered all-warp compaction (ascending face ids preserved)
        int cnt = 0;
        for (int base = 0; base < chunk; base += 256) {
            int f = base + tid;
            bool ok = false;
            if (f < chunk) {
                float4 bb = bb_g[f0 + f];
                ok = (bb.x <= tx1) && (bb.y >= tx0) &&
                     (bb.z <= ty1) && (bb.w >= ty0);
            }
            unsigned m = __ballot_sync(0xffffffffu, ok);
            int lanePfx = __popc(m & ((1u << lane) - 1u));
            if (lane == 0) swcnt[warp] = __popc(m);
            __syncthreads();
            int wbase = cnt;
#pragma unroll
            for (int w = 0; w < 8; w++) {
                int c = swcnt[w];
                if (w < warp) wbase += c;
                cnt += c;
            }
            if (ok) slist[wbase + lanePfx] = f0 + f;
            __syncthreads();
        }
        const int nf = cnt;

        // gather listed faces into smem
        for (int i = tid; i < nf; i += 256) {
            int f = slist[i];
            sa[i]  = fa_g[f];
            sb[i]  = fb_g[f];
            scz[i] = fc_g[f].x;
        }
        __syncthreads();

        if (active) {
            int best_i = -1;
#pragma unroll 2
            for (int i = 0; i < nf; i++) {
                const float4 fa = sa[i];
                const float4 fb = sb[i];
                const float  cz = scz[i];
                float w1 = fmaf(fa.x, px, fmaf(fa.y, py, fa.z));
                float w2 = fmaf(fa.w, px, fmaf(fb.x, py, fb.y));
                float iv = fmaf(fb.z, px, fmaf(fb.w, py, cz));
                float w0 = 1.0f - w1 - w2;
                // NaN-safe explicit compares (NaN>=0 is false)
                if (w0 >= 0.0f && w1 >= 0.0f && w2 >= 0.0f && iv > best_iv) {
                    best_iv = iv;
                    best_i  = i;
                }
            }
            if (best_i >= 0) best_face = slist[best_i];
        }
        __syncthreads();
    }

    // Second pass: perspective-correct trilinear texture + squared error.
    float lsum = 0.0f;
    if (active) {
        float c0 = 0.0f, c1 = 0.0f, c2 = 0.0f;
        int f = best_face;
        if (f >= 0) {
            const float4 fa = fa_g[f];
            const float4 fb = fb_g[f];
            const float4 fc = fc_g[f];
            float w1 = fmaf(fa.x, px, fmaf(fa.y, py, fa.z));
            float w2 = fmaf(fa.w, px, fmaf(fb.x, py, fb.y));
            float iv = fmaf(fb.z, px, fmaf(fb.w, py, fc.x));
            float w0 = 1.0f - w1 - w2;
            float iz = fmaxf(iv, EPSF);
            float r  = 1.0f / iz;
            float wp0 = __saturatef(w0 * fc.y * r);
            float wp1 = __saturatef(w1 * fc.z * r);
            float wp2 = __saturatef(w2 * fc.w * r);
            float q0 = 1.0f - wp0, q1 = 1.0f - wp1, q2 = 1.0f - wp2;
            float wA = q0 * q1, wB = q0 * wp1, wC = wp0 * q1, wD = wp0 * wp1;
            float w000 = wA * q2, w001 = wA * wp2;
            float w010 = wB * q2, w011 = wB * wp2;
            float w100 = wC * q2, w101 = wC * wp2;
            float w110 = wD * q2, w111 = wD * wp2;

            float tv[24];
#pragma unroll
            for (int q = 0; q < 6; q++) {
                float4 v = g_tex4[f * 6 + q];
                tv[q * 4 + 0] = v.x; tv[q * 4 + 1] = v.y;
                tv[q * 4 + 2] = v.z; tv[q * 4 + 3] = v.w;
            }
#pragma unroll
            for (int c = 0; c < 3; c++) {
                float col = w000 * tv[0 + c]  + w001 * tv[3 + c]
                          + w010 * tv[6 + c]  + w011 * tv[9 + c]
                          + w100 * tv[12 + c] + w101 * tv[15 + c]
                          + w110 * tv[18 + c] + w111 * tv[21 + c];
                if (c == 0) c0 = col; else if (c == 1) c1 = col; else c2 = col;
            }
        }
        float rv0 = image_ref[((size_t)(b * 3 + 0) * S + y) * S + x];
        float rv1 = image_ref[((size_t)(b * 3 + 1) * S + y) * S + x];
        float rv2 = image_ref[((size_t)(b * 3 + 2) * S + y) * S + x];
        float d0 = c0 - rv0, d1 = c1 - rv1, d2 = c2 - rv2;
        lsum = d0 * d0 + d1 * d1 + d2 * d2;
    }

    // deterministic block reduction (8 warps)
#pragma unroll
    for (int o = 16; o > 0; o >>= 1)
        lsum += __shfl_down_sync(0xffffffffu, lsum, o);
    if (lane == 0) swred[warp] = lsum;
    __syncthreads();
    if (warp == 0) {
        float s = (lane < 8) ? swred[lane] : 0.0f;
#pragma unroll
        for (int o = 4; o > 0; o >>= 1)
            s += __shfl_down_sync(0xffffffffu, s, o);
        if (lane == 0)
            g_part[(size_t)blockIdx.z * gridDim.x * gridDim.y
                   + blockIdx.y * gridDim.x + blockIdx.x] = s;
    }
}

__global__ void reduce_kernel(float* __restrict__ out, int nb) {
    __shared__ float sred[256];
    float s = 0.0f;
    for (int i = threadIdx.x; i < nb; i += 256) s += g_part[i];
    sred[threadIdx.x] = s;
    __syncthreads();
#pragma unroll
    for (int k = 128; k > 0; k >>= 1) {
        if (threadIdx.x < k) sred[threadIdx.x] += sred[threadIdx.x + k];
        __syncthreads();
    }
    if (threadIdx.x == 0) out[0] = sred[0];
}

extern "C" void kernel_launch(void* const* d_in, const int* in_sizes, int n_in,
                              void* d_out, int out_size) {
    const float* vertices  = (const float*)d_in[0];
    const int*   faces     = (const int*)  d_in[1];
    const float* Kmat      = (const float*)d_in[2];
    const float* Rmat      = (const float*)d_in[3];
    const float* tvec      = (const float*)d_in[4];
    const float* textures  = (const float*)d_in[5];
    const float* image_ref = (const float*)d_in[6];

    int B = in_sizes[2] / 9;                 // K is (B,3,3)
    int V = in_sizes[0] / (3 * B);
    int F = in_sizes[1] / (3 * B);
    int ss = in_sizes[6] / (3 * B);          // S*S
    int S = (int)(sqrt((double)ss) + 0.5);

    float* out = (float*)d_out;

    int prepN = (B * F > F * 6) ? B * F : F * 6;
    prep_kernel<<<(prepN + 255) / 256, 256>>>(vertices, faces, Kmat, Rmat,
                                              tvec, textures, B, V, F, S);

    dim3 blk(16, 16);
    dim3 grd((S + 15) / 16, (S + 15) / 16, B);
    raster_kernel<<<grd, blk>>>(image_ref, B, F, S);

    int nb = grd.x * grd.y * grd.z;
    reduce_kernel<<<1, 256>>>(out, nb);
}

// round 4
// speedup vs baseline: 2.1785x; 1.2708x over previous
#include <cuda_runtime.h>
#include <math.h>

#define EPSF 1e-9f
#define MAXF 4096
#define MAXB 8
#define FCHUNK 1024

// Per-face affine coefficients (precomputed in prep):
//   w1(px,py) = A1*px + B1*py + C1
//   w2(px,py) = A2*px + B2*py + C2
//   invz(px,py) = Az*px + Bz*py + Cz
// fa = (A1,B1,C1,A2), fb = (B2,C2,Az,Bz), fc = (Cz,1/z0,1/z1,1/z2), cz = Cz
// C1 NaN-poisoned when invalid/backface -> every >= compare fails -> culled.
__device__ float4 g_fa[MAXB * MAXF];
__device__ float4 g_fb[MAXB * MAXF];
__device__ float4 g_fc[MAXB * MAXF];
__device__ float  g_cz[MAXB * MAXF];
__device__ float4 g_tex4[MAXF * 6];       // tanh(textures), 24 floats/face
__device__ float  g_part[8192];
__device__ int    g_cnt = 0;

__global__ void prep_kernel(const float* __restrict__ verts,
                            const int*   __restrict__ faces,
                            const float* __restrict__ Kmat,
                            const float* __restrict__ Rmat,
                            const float* __restrict__ tvec,
                            const float* __restrict__ textures,
                            int B, int V, int F, int S) {
    int idx = blockIdx.x * blockDim.x + threadIdx.x;
    int stride = gridDim.x * blockDim.x;

    int texN4 = F * 6;
    const float4* t4 = (const float4*)textures;
    for (int i = idx; i < texN4; i += stride) {
        float4 v = t4[i];
        g_tex4[i] = make_float4(tanhf(v.x), tanhf(v.y), tanhf(v.z), tanhf(v.w));
    }

    if (idx >= B * F) return;
    int b = idx / F;
    int f = idx - b * F;

    const float* Rb = Rmat + b * 9;
    const float* Kb = Kmat + b * 9;
    const float* tb = tvec + b * 3;

    float xs[3], ys[3], zs[3];
#pragma unroll
    for (int vi = 0; vi < 3; vi++) {
        int vid = faces[(b * F + f) * 3 + vi];
        const float* p = verts + ((size_t)b * V + vid) * 3;
        float px = p[0], py = p[1], pz = p[2];
        float vx = Rb[0] * px + Rb[1] * py + Rb[2] * pz + tb[0];
        float vy = Rb[3] * px + Rb[4] * py + Rb[5] * pz + tb[1];
        float vz = Rb[6] * px + Rb[7] * py + Rb[8] * pz + tb[2];
        float xh = vx / (vz + EPSF);
        float yh = vy / (vz + EPSF);
        float u  = Kb[0] * xh + Kb[1] * yh + Kb[2];
        float pv = Kb[3] * xh + Kb[4] * yh + Kb[5];
        float v  = (float)S - pv;
        u = 2.0f * (u - 0.5f * (float)S) / (float)S;
        v = 2.0f * (v - 0.5f * (float)S) / (float)S;
        xs[vi] = u; ys[vi] = v; zs[vi] = vz;
    }

    float e1x = xs[1] - xs[0], e1y = ys[1] - ys[0];
    float e2x = xs[2] - xs[0], e2y = ys[2] - ys[0];
    float den = e1x * e2y - e2x * e1y;
    bool valid = fabsf(den) > 1e-8f;
    float dens = valid ? den : 1.0f;
    bool front = fminf(zs[0], fminf(zs[1], zs[2])) > EPSF;
    float rden = 1.0f / dens;

    float A1 =  e2y * rden;
    float B1 = -e2x * rden;
    float C1 = (ys[0] * e2x - xs[0] * e2y) * rden;
    float A2 = -e1y * rden;
    float B2 =  e1x * rden;
    float C2 = (xs[0] * e1y - ys[0] * e1x) * rden;

    float iz0 = 1.0f / zs[0], iz1 = 1.0f / zs[1], iz2 = 1.0f / zs[2];
    float d1 = iz1 - iz0, d2 = iz2 - iz0;
    float Az = A1 * d1 + A2 * d2;
    float Bz = B1 * d1 + B2 * d2;
    float Cz = iz0 + C1 * d1 + C2 * d2;

    if (!(valid && front)) C1 = __int_as_float(0x7FC00000);  // NaN

    g_fa[idx] = make_float4(A1, B1, C1, A2);
    g_fb[idx] = make_float4(B2, C2, Az, Bz);
    g_fc[idx] = make_float4(Cz, iz0, iz1, iz2);
    g_cz[idx] = Cz;
}

// block (16,16) = 256 threads = 8 warps; tile = 16x16 pixels; 1 px/thread.
__global__ void raster_kernel(const float* __restrict__ image_ref,
                              float* __restrict__ out,
                              int B, int F, int S) {
    __shared__ int    slist[FCHUNK];
    __shared__ float4 sa[FCHUNK];
    __shared__ float4 sb[FCHUNK];
    __shared__ float  sc[FCHUNK];
    __shared__ int    swcnt[8];
    __shared__ float  swred[8];
    __shared__ int    slast;

    const int b    = blockIdx.z;
    const int tid  = threadIdx.y * 16 + threadIdx.x;
    const int warp = tid >> 5;
    const int lane = tid & 31;
    const int x    = blockIdx.x * 16 + threadIdx.x;
    const int y    = blockIdx.y * 16 + threadIdx.y;
    const float invS = 1.0f / (float)S;
    const float py = (2.0f * (float)y + 1.0f - (float)S) * invS;
    const float px = (2.0f * (float)x + 1.0f - (float)S) * invS;
    const bool active = (x < S) && (y < S);

    // pixel-center rectangle of this tile: center + half extents (NDC)
    const float cxc = (2.0f * ((float)(blockIdx.x * 16) + 7.5f) + 1.0f - (float)S) * invS;
    const float cyc = (2.0f * ((float)(blockIdx.y * 16) + 7.5f) + 1.0f - (float)S) * invS;
    const float hw  = 15.0f * invS;   // 7.5 * (2/S)
    const float hh  = 15.0f * invS;

    const float4* fa_g = g_fa + (size_t)b * F;
    const float4* fb_g = g_fb + (size_t)b * F;
    const float4* fc_g = g_fc + (size_t)b * F;
    const float*  cz_g = g_cz + (size_t)b * F;

    float best_iv  = EPSF;
    int   best_face = -1;

    for (int f0 = 0; f0 < F; f0 += FCHUNK) {
        const int chunk = min(FCHUNK, F - f0);

        // fused exact-halfplane cull + ordered compaction + staging
        int cnt = 0;
        for (int base = 0; base < chunk; base += 256) {
            int f = base + tid;
            bool ok = false;
            float4 fa, fb;
            if (f < chunk) {
                fa = fa_g[f0 + f];
                fb = fb_g[f0 + f];
                // max over tile of each barycentric (affine) >= 0 ?
                float w1c = fmaf(fa.x, cxc, fmaf(fa.y, cyc, fa.z));
                float w2c = fmaf(fa.w, cxc, fmaf(fb.x, cyc, fb.y));
                float r1  = fmaf(fabsf(fa.x), hw, fabsf(fa.y) * hh);
                float r2  = fmaf(fabsf(fa.w), hw, fabsf(fb.x) * hh);
                float a0  = fa.x + fa.w, b0 = fa.y + fb.x;
                float w0c = 1.0f - w1c - w2c;
                float r0  = fmaf(fabsf(a0), hw, fabsf(b0) * hh);
                // NaN-poisoned C1 -> w1c NaN -> all compares false -> culled
                ok = (w1c + r1 >= 0.0f) && (w2c + r2 >= 0.0f) && (w0c + r0 >= 0.0f);
            }
            unsigned m = __ballot_sync(0xffffffffu, ok);
            int lanePfx = __popc(m & ((1u << lane) - 1u));
            if (lane == 0) swcnt[warp] = __popc(m);
            __syncthreads();
            int wbase = cnt;
#pragma unroll
            for (int w = 0; w < 8; w++) {
                int c = swcnt[w];
                if (w < warp) wbase += c;
                cnt += c;
            }
            if (ok) {
                int pos = wbase + lanePfx;
                slist[pos] = f0 + f;
                sa[pos] = fa;
                sb[pos] = fb;
                sc[pos] = cz_g[f0 + f];
            }
            __syncthreads();
        }
        const int nf = cnt;

        if (active) {
            int best_i = -1;
#pragma unroll 2
            for (int i = 0; i < nf; i++) {
                const float4 fa = sa[i];
                const float4 fb = sb[i];
                const float  cz = sc[i];
                float w1 = fmaf(fa.x, px, fmaf(fa.y, py, fa.z));
                float w2 = fmaf(fa.w, px, fmaf(fb.x, py, fb.y));
                float iv = fmaf(fb.z, px, fmaf(fb.w, py, cz));
                float s  = w1 + w2;
                if (w1 >= 0.0f && w2 >= 0.0f && s <= 1.0f && iv > best_iv) {
                    best_iv = iv;
                    best_i  = i;
                }
            }
            if (best_i >= 0) best_face = slist[best_i];
        }
        __syncthreads();
    }

    // perspective-correct trilinear texture + squared error
    float lsum = 0.0f;
    if (active) {
        float c0 = 0.0f, c1 = 0.0f, c2 = 0.0f;
        int f = best_face;
        if (f >= 0) {
            const float4 fa = fa_g[f];
            const float4 fb = fb_g[f];
            const float4 fc = fc_g[f];
            float w1 = fmaf(fa.x, px, fmaf(fa.y, py, fa.z));
            float w2 = fmaf(fa.w, px, fmaf(fb.x, py, fb.y));
            float iv = fmaf(fb.z, px, fmaf(fb.w, py, fc.x));
            float w0 = 1.0f - w1 - w2;
            float iz = fmaxf(iv, EPSF);
            float r  = 1.0f / iz;
            float wp0 = __saturatef(w0 * fc.y * r);
            float wp1 = __saturatef(w1 * fc.z * r);
            float wp2 = __saturatef(w2 * fc.w * r);
            float q0 = 1.0f - wp0, q1 = 1.0f - wp1, q2 = 1.0f - wp2;
            float wA = q0 * q1, wB = q0 * wp1, wC = wp0 * q1, wD = wp0 * wp1;
            float w000 = wA * q2, w001 = wA * wp2;
            float w010 = wB * q2, w011 = wB * wp2;
            float w100 = wC * q2, w101 = wC * wp2;
            float w110 = wD * q2, w111 = wD * wp2;

            float tv[24];
#pragma unroll
            for (int q = 0; q < 6; q++) {
                float4 v = g_tex4[f * 6 + q];
                tv[q * 4 + 0] = v.x; tv[q * 4 + 1] = v.y;
                tv[q * 4 + 2] = v.z; tv[q * 4 + 3] = v.w;
            }
#pragma unroll
            for (int c = 0; c < 3; c++) {
                float col = w000 * tv[0 + c]  + w001 * tv[3 + c]
                          + w010 * tv[6 + c]  + w011 * tv[9 + c]
                          + w100 * tv[12 + c] + w101 * tv[15 + c]
                          + w110 * tv[18 + c] + w111 * tv[21 + c];
                if (c == 0) c0 = col; else if (c == 1) c1 = col; else c2 = col;
            }
        }
        float rv0 = image_ref[((size_t)(b * 3 + 0) * S + y) * S + x];
        float rv1 = image_ref[((size_t)(b * 3 + 1) * S + y) * S + x];
        float rv2 = image_ref[((size_t)(b * 3 + 2) * S + y) * S + x];
        float d0 = c0 - rv0, d1 = c1 - rv1, d2 = c2 - rv2;
        lsum = d0 * d0 + d1 * d1 + d2 * d2;
    }

    // deterministic block reduction
#pragma unroll
    for (int o = 16; o > 0; o >>= 1)
        lsum += __shfl_down_sync(0xffffffffu, lsum, o);
    if (lane == 0) swred[warp] = lsum;
    __syncthreads();

    const int nb = gridDim.x * gridDim.y * gridDim.z;
    const int bid = blockIdx.z * gridDim.x * gridDim.y
                  + blockIdx.y * gridDim.x + blockIdx.x;
    if (tid == 0) {
        float s = 0.0f;
#pragma unroll
        for (int w = 0; w < 8; w++) s += swred[w];
        g_part[bid] = s;
        __threadfence();
        int t = atomicAdd(&g_cnt, 1);
        slast = (t == nb - 1);
    }
    __syncthreads();

    // last block: deterministic fixed-order final reduction
    if (slast) {
        float s = 0.0f;
        for (int i = tid; i < nb; i += 256) s += g_part[i];
#pragma unroll
        for (int o = 16; o > 0; o >>= 1)
            s += __shfl_down_sync(0xffffffffu, s, o);
        if (lane == 0) swred[warp] = s;
        __syncthreads();
        if (tid == 0) {
            float tot = 0.0f;
#pragma unroll
            for (int w = 0; w < 8; w++) tot += swred[w];
            out[0] = tot;
            g_cnt = 0;   // reset for next graph replay
        }
    }
}

extern "C" void kernel_launch(void* const* d_in, const int* in_sizes, int n_in,
                              void* d_out, int out_size) {
    const float* vertices  = (const float*)d_in[0];
    const int*   faces     = (const int*)  d_in[1];
    const float* Kmat      = (const float*)d_in[2];
    const float* Rmat      = (const float*)d_in[3];
    const float* tvec      = (const float*)d_in[4];
    const float* textures  = (const float*)d_in[5];
    const float* image_ref = (const float*)d_in[6];

    int B = in_sizes[2] / 9;
    int V = in_sizes[0] / (3 * B);
    int F = in_sizes[1] / (3 * B);
    int ss = in_sizes[6] / (3 * B);
    int S = (int)(sqrt((double)ss) + 0.5);

    float* out = (float*)d_out;

    int prepN = (B * F > F * 6) ? B * F : F * 6;
    prep_kernel<<<(prepN + 255) / 256, 256>>>(vertices, faces, Kmat, Rmat,
                                              tvec, textures, B, V, F, S);

    dim3 blk(16, 16);
    dim3 grd((S + 15) / 16, (S + 15) / 16, B);
    raster_kernel<<<grd, blk>>>(image_ref, out, B, F, S);
}

// round 5
// speedup vs baseline: 2.3315x; 1.0703x over previous
#include <cuda_runtime.h>
#include <math.h>

#define EPSF 1e-9f
#define MAXF 4096
#define MAXB 8
#define FCAP 1024   // smem face capacity (>= F)

// Per-face affine coefficients (precomputed in prep):
//   w1(px,py) = A1*px + B1*py + C1
//   w2(px,py) = A2*px + B2*py + C2
//   invz(px,py) = Az*px + Bz*py + Cz
// fa = (A1,B1,C1,A2), fb = (B2,C2,Az,Bz), fc = (Cz,1/z0,1/z1,1/z2), cz = Cz
// C1 NaN-poisoned when invalid/backface -> every >= compare fails -> culled.
__device__ float4 g_fa[MAXB * MAXF];
__device__ float4 g_fb[MAXB * MAXF];
__device__ float4 g_fc[MAXB * MAXF];
__device__ float  g_cz[MAXB * MAXF];
__device__ float4 g_tex4[MAXF * 6];
__device__ float  g_part[8192];
__device__ int    g_cnt = 0;

__global__ void prep_kernel(const float* __restrict__ verts,
                            const int*   __restrict__ faces,
                            const float* __restrict__ Kmat,
                            const float* __restrict__ Rmat,
                            const float* __restrict__ tvec,
                            const float* __restrict__ textures,
                            int B, int V, int F, int S) {
    int idx = blockIdx.x * blockDim.x + threadIdx.x;
    int stride = gridDim.x * blockDim.x;

    // one tanh per thread (short dependency chains, many warps)
    int texN = F * 24;
    float* texo = (float*)g_tex4;
    for (int i = idx; i < texN; i += stride)
        texo[i] = tanhf(textures[i]);

    if (idx >= B * F) return;
    int b = idx / F;
    int f = idx - b * F;

    const float* Rb = Rmat + b * 9;
    const float* Kb = Kmat + b * 9;
    const float* tb = tvec + b * 3;

    float xs[3], ys[3], zs[3];
#pragma unroll
    for (int vi = 0; vi < 3; vi++) {
        int vid = faces[(b * F + f) * 3 + vi];
        const float* p = verts + ((size_t)b * V + vid) * 3;
        float px = p[0], py = p[1], pz = p[2];
        float vx = Rb[0] * px + Rb[1] * py + Rb[2] * pz + tb[0];
        float vy = Rb[3] * px + Rb[4] * py + Rb[5] * pz + tb[1];
        float vz = Rb[6] * px + Rb[7] * py + Rb[8] * pz + tb[2];
        float xh = vx / (vz + EPSF);
        float yh = vy / (vz + EPSF);
        float u  = Kb[0] * xh + Kb[1] * yh + Kb[2];
        float pv = Kb[3] * xh + Kb[4] * yh + Kb[5];
        float v  = (float)S - pv;
        u = 2.0f * (u - 0.5f * (float)S) / (float)S;
        v = 2.0f * (v - 0.5f * (float)S) / (float)S;
        xs[vi] = u; ys[vi] = v; zs[vi] = vz;
    }

    float e1x = xs[1] - xs[0], e1y = ys[1] - ys[0];
    float e2x = xs[2] - xs[0], e2y = ys[2] - ys[0];
    float den = e1x * e2y - e2x * e1y;
    bool valid = fabsf(den) > 1e-8f;
    float dens = valid ? den : 1.0f;
    bool front = fminf(zs[0], fminf(zs[1], zs[2])) > EPSF;
    float rden = 1.0f / dens;

    float A1 =  e2y * rden;
    float B1 = -e2x * rden;
    float C1 = (ys[0] * e2x - xs[0] * e2y) * rden;
    float A2 = -e1y * rden;
    float B2 =  e1x * rden;
    float C2 = (xs[0] * e1y - ys[0] * e1x) * rden;

    float iz0 = 1.0f / zs[0], iz1 = 1.0f / zs[1], iz2 = 1.0f / zs[2];
    float d1 = iz1 - iz0, d2 = iz2 - iz0;
    float Az = A1 * d1 + A2 * d2;
    float Bz = B1 * d1 + B2 * d2;
    float Cz = iz0 + C1 * d1 + C2 * d2;

    if (!(valid && front)) C1 = __int_as_float(0x7FC00000);  // NaN

    g_fa[idx] = make_float4(A1, B1, C1, A2);
    g_fb[idx] = make_float4(B2, C2, Az, Bz);
    g_fc[idx] = make_float4(Cz, iz0, iz1, iz2);
    g_cz[idx] = Cz;
}

// block (16,16,2) = 512 threads = 16 warps; tile = 16x16 px; 2 face-slices.
__global__ void __launch_bounds__(512, 3)
raster_kernel(const float* __restrict__ image_ref,
              float* __restrict__ out,
              int B, int F, int S) {
    __shared__ int    slist[FCAP];
    __shared__ float4 sa[FCAP];
    __shared__ float4 sb[FCAP];
    __shared__ float  sc[FCAP];
    __shared__ int    swcnt[16];
    __shared__ float  swred[16];
    __shared__ float  smiv[256];
    __shared__ int    smfc[256];
    __shared__ int    slast;

    const int b     = blockIdx.z;
    const int slice = threadIdx.z;
    const int pix   = threadIdx.y * 16 + threadIdx.x;
    const int tid   = slice * 256 + pix;
    const int warp  = tid >> 5;
    const int lane  = tid & 31;
    const int x     = blockIdx.x * 16 + threadIdx.x;
    const int y     = blockIdx.y * 16 + threadIdx.y;
    const float invS = 1.0f / (float)S;
    const float py = (2.0f * (float)y + 1.0f - (float)S) * invS;
    const float px = (2.0f * (float)x + 1.0f - (float)S) * invS;
    const bool active = (x < S) && (y < S);

    // tile rect (pixel centers): center + half extents in NDC
    const float cxc = (2.0f * ((float)(blockIdx.x * 16) + 7.5f) + 1.0f - (float)S) * invS;
    const float cyc = (2.0f * ((float)(blockIdx.y * 16) + 7.5f) + 1.0f - (float)S) * invS;
    const float hw  = 15.0f * invS;
    const float hh  = 15.0f * invS;

    const float4* fa_g = g_fa + (size_t)b * F;
    const float4* fb_g = g_fb + (size_t)b * F;
    const float4* fc_g = g_fc + (size_t)b * F;
    const float*  cz_g = g_cz + (size_t)b * F;

    // fused exact-halfplane cull + ordered compaction + staging (512 wide)
    int cnt = 0;
    for (int base = 0; base < F; base += 512) {
        int f = base + tid;
        bool ok = false;
        float4 fa, fb;
        if (f < F) {
            fa = fa_g[f];
            fb = fb_g[f];
            float w1c = fmaf(fa.x, cxc, fmaf(fa.y, cyc, fa.z));
            float w2c = fmaf(fa.w, cxc, fmaf(fb.x, cyc, fb.y));
            float r1  = fmaf(fabsf(fa.x), hw, fabsf(fa.y) * hh);
            float r2  = fmaf(fabsf(fa.w), hw, fabsf(fb.x) * hh);
            float a0  = fa.x + fa.w, b0 = fa.y + fb.x;
            float w0c = 1.0f - w1c - w2c;
            float r0  = fmaf(fabsf(a0), hw, fabsf(b0) * hh);
            ok = (w1c + r1 >= 0.0f) && (w2c + r2 >= 0.0f) && (w0c + r0 >= 0.0f);
        }
        unsigned m = __ballot_sync(0xffffffffu, ok);
        int lanePfx = __popc(m & ((1u << lane) - 1u));
        if (lane == 0) swcnt[warp] = __popc(m);
        __syncthreads();
        int wbase = cnt;
#pragma unroll
        for (int w = 0; w < 16; w++) {
            int c = swcnt[w];
            if (w < warp) wbase += c;
            cnt += c;
        }
        if (ok) {
            int pos = wbase + lanePfx;
            slist[pos] = f;
            sa[pos] = fa;
            sb[pos] = fb;
            sc[pos] = cz_g[f];
        }
        __syncthreads();
    }
    const int nf = cnt;

    // each slice scans its parity of compacted faces
    float best_iv = EPSF;
    int   best_i  = -1;
    if (active) {
#pragma unroll 2
        for (int i = slice; i < nf; i += 2) {
            const float4 fa = sa[i];
            const float4 fb = sb[i];
            const float  cz = sc[i];
            float w1 = fmaf(fa.x, px, fmaf(fa.y, py, fa.z));
            float w2 = fmaf(fa.w, px, fmaf(fb.x, py, fb.y));
            float iv = fmaf(fb.z, px, fmaf(fb.w, py, cz));
            float s  = w1 + w2;
            if (w1 >= 0.0f && w2 >= 0.0f && s <= 1.0f && iv > best_iv) {
                best_iv = iv;
                best_i  = i;
            }
        }
    }
    int best_face = (best_i >= 0) ? slist[best_i] : -1;

    // deterministic cross-slice merge: max invz, ties -> smaller face id
    if (slice == 1) { smiv[pix] = best_iv; smfc[pix] = best_face; }
    __syncthreads();
    if (slice == 0) {
        float iv1 = smiv[pix];
        int   f1  = smfc[pix];
        if (f1 >= 0 && (best_face < 0 || iv1 > best_iv ||
                        (iv1 == best_iv && f1 < best_face))) {
            best_iv   = iv1;
            best_face = f1;
        }
    }

    // epilogue on slice 0: perspective-correct trilinear texture + sq error
    float lsum = 0.0f;
    if (slice == 0 && active) {
        float c0 = 0.0f, c1 = 0.0f, c2 = 0.0f;
        int f = best_face;
        if (f >= 0) {
            const float4 fa = fa_g[f];
            const float4 fb = fb_g[f];
            const float4 fc = fc_g[f];
            float w1 = fmaf(fa.x, px, fmaf(fa.y, py, fa.z));
            float w2 = fmaf(fa.w, px, fmaf(fb.x, py, fb.y));
            float iv = fmaf(fb.z, px, fmaf(fb.w, py, fc.x));
            float w0 = 1.0f - w1 - w2;
            float iz = fmaxf(iv, EPSF);
            float r  = 1.0f / iz;
            float wp0 = __saturatef(w0 * fc.y * r);
            float wp1 = __saturatef(w1 * fc.z * r);
            float wp2 = __saturatef(w2 * fc.w * r);
            float q0 = 1.0f - wp0, q1 = 1.0f - wp1, q2 = 1.0f - wp2;
            float wA = q0 * q1, wB = q0 * wp1, wC = wp0 * q1, wD = wp0 * wp1;
            float w000 = wA * q2, w001 = wA * wp2;
            float w010 = wB * q2, w011 = wB * wp2;
            float w100 = wC * q2, w101 = wC * wp2;
            float w110 = wD * q2, w111 = wD * wp2;

            float tv[24];
#pragma unroll
            for (int q = 0; q < 6; q++) {
                float4 v = g_tex4[f * 6 + q];
                tv[q * 4 + 0] = v.x; tv[q * 4 + 1] = v.y;
                tv[q * 4 + 2] = v.z; tv[q * 4 + 3] = v.w;
            }
#pragma unroll
            for (int c = 0; c < 3; c++) {
                float col = w000 * tv[0 + c]  + w001 * tv[3 + c]
                          + w010 * tv[6 + c]  + w011 * tv[9 + c]
                          + w100 * tv[12 + c] + w101 * tv[15 + c]
                          + w110 * tv[18 + c] + w111 * tv[21 + c];
                if (c == 0) c0 = col; else if (c == 1) c1 = col; else c2 = col;
            }
        }
        float rv0 = image_ref[((size_t)(b * 3 + 0) * S + y) * S + x];
        float rv1 = image_ref[((size_t)(b * 3 + 1) * S + y) * S + x];
        float rv2 = image_ref[((size_t)(b * 3 + 2) * S + y) * S + x];
        float d0 = c0 - rv0, d1 = c1 - rv1, d2 = c2 - rv2;
        lsum = d0 * d0 + d1 * d1 + d2 * d2;
    }

    // deterministic block reduction (16 warps; slice1 contributes 0)
#pragma unroll
    for (int o = 16; o > 0; o >>= 1)
        lsum += __shfl_down_sync(0xffffffffu, lsum, o);
    if (lane == 0) swred[warp] = lsum;
    __syncthreads();

    const int nb = gridDim.x * gridDim.y * gridDim.z;
    const int bid = blockIdx.z * gridDim.x * gridDim.y
                  + blockIdx.y * gridDim.x + blockIdx.x;
    if (tid == 0) {
        float s = 0.0f;
#pragma unroll
        for (int w = 0; w < 16; w++) s += swred[w];
        g_part[bid] = s;
        __threadfence();
        int t = atomicAdd(&g_cnt, 1);
        slast = (t == nb - 1);
    }
    __syncthreads();

    // last block: deterministic fixed-order final reduction
    if (slast) {
        float s = 0.0f;
        for (int i = tid; i < nb; i += 512) s += g_part[i];
#pragma unroll
        for (int o = 16; o > 0; o >>= 1)
            s += __shfl_down_sync(0xffffffffu, s, o);
        if (lane == 0) swred[warp] = s;
        __syncthreads();
        if (tid == 0) {
            float tot = 0.0f;
#pragma unroll
            for (int w = 0; w < 16; w++) tot += swred[w];
            out[0] = tot;
            g_cnt = 0;   // reset for next graph replay
        }
    }
}

extern "C" void kernel_launch(void* const* d_in, const int* in_sizes, int n_in,
                              void* d_out, int out_size) {
    const float* vertices  = (const float*)d_in[0];
    const int*   faces     = (const int*)  d_in[1];
    const float* Kmat      = (const float*)d_in[2];
    const float* Rmat      = (const float*)d_in[3];
    const float* tvec      = (const float*)d_in[4];
    const float* textures  = (const float*)d_in[5];
    const float* image_ref = (const float*)d_in[6];

    int B = in_sizes[2] / 9;
    int V = in_sizes[0] / (3 * B);
    int F = in_sizes[1] / (3 * B);
    int ss = in_sizes[6] / (3 * B);
    int S = (int)(sqrt((double)ss) + 0.5);

    float* out = (float*)d_out;

    int prepN = (B * F > F * 24) ? B * F : F * 24;
    prep_kernel<<<(prepN + 255) / 256, 256>>>(vertices, faces, Kmat, Rmat,
                                              tvec, textures, B, V, F, S);

    dim3 blk(16, 16, 2);
    dim3 grd((S + 15) / 16, (S + 15) / 16, B);
    raster_kernel<<<grd, blk>>>(image_ref, out, B, F, S);
}

// round 6
// speedup vs baseline: 2.5077x; 1.0756x over previous
#include <cuda_runtime.h>
#include <math.h>

#define EPSF 1e-9f
#define MAXF 4096
#define MAXB 8
#define FCAP 1024
#define MAXBV 2048   // max B*V vertices cached in prep smem

// fa = (A1,B1,C1,A2), fb = (B2,C2,Az,Bz), fc = (Cz,1/z0,1/z1,1/z2), cz = Cz
// C1 NaN-poisoned when invalid/backface -> every >= compare fails -> culled.
__device__ float4 g_fa[MAXB * MAXF];
__device__ float4 g_fb[MAXB * MAXF];
__device__ float4 g_fc[MAXB * MAXF];
__device__ float  g_cz[MAXB * MAXF];
__device__ float4 g_tex4[MAXF * 6];
__device__ float  g_part[8192];
__device__ int    g_cnt = 0;

__global__ void prep_kernel(const float* __restrict__ verts,
                            const int*   __restrict__ faces,
                            const float* __restrict__ Kmat,
                            const float* __restrict__ Rmat,
                            const float* __restrict__ tvec,
                            const float* __restrict__ textures,
                            int B, int V, int F, int S) {
    __shared__ float sv[MAXBV * 3];

    int idx = blockIdx.x * blockDim.x + threadIdx.x;
    int stride = gridDim.x * blockDim.x;

    const bool faceblock = (blockIdx.x * blockDim.x < B * F);
    const bool use_sv = faceblock && (B * V <= MAXBV);
    if (use_sv) {
        int n = B * V * 3;
        for (int i = threadIdx.x; i < n; i += blockDim.x) sv[i] = verts[i];
        __syncthreads();
    }

    // tanh (one element per thread pass)
    int texN = F * 24;
    float* texo = (float*)g_tex4;
    for (int i = idx; i < texN; i += stride)
        texo[i] = tanhf(textures[i]);

    if (idx >= B * F) return;
    int b = idx / F;
    int f = idx - b * F;

    const float* Rb = Rmat + b * 9;
    const float* Kb = Kmat + b * 9;
    const float* tb = tvec + b * 3;

    float xs[3], ys[3], zs[3];
#pragma unroll
    for (int vi = 0; vi < 3; vi++) {
        int vid = faces[(b * F + f) * 3 + vi];
        const float* p = use_sv ? (sv + ((size_t)b * V + vid) * 3)
                                : (verts + ((size_t)b * V + vid) * 3);
        float px = p[0], py = p[1], pz = p[2];
        float vx = Rb[0] * px + Rb[1] * py + Rb[2] * pz + tb[0];
        float vy = Rb[3] * px + Rb[4] * py + Rb[5] * pz + tb[1];
        float vz = Rb[6] * px + Rb[7] * py + Rb[8] * pz + tb[2];
        float xh = vx / (vz + EPSF);
        float yh = vy / (vz + EPSF);
        float u  = Kb[0] * xh + Kb[1] * yh + Kb[2];
        float pv = Kb[3] * xh + Kb[4] * yh + Kb[5];
        float v  = (float)S - pv;
        u = 2.0f * (u - 0.5f * (float)S) / (float)S;
        v = 2.0f * (v - 0.5f * (float)S) / (float)S;
        xs[vi] = u; ys[vi] = v; zs[vi] = vz;
    }

    float e1x = xs[1] - xs[0], e1y = ys[1] - ys[0];
    float e2x = xs[2] - xs[0], e2y = ys[2] - ys[0];
    float den = e1x * e2y - e2x * e1y;
    bool valid = fabsf(den) > 1e-8f;
    float dens = valid ? den : 1.0f;
    bool front = fminf(zs[0], fminf(zs[1], zs[2])) > EPSF;
    float rden = 1.0f / dens;

    float A1 =  e2y * rden;
    float B1 = -e2x * rden;
    float C1 = (ys[0] * e2x - xs[0] * e2y) * rden;
    float A2 = -e1y * rden;
    float B2 =  e1x * rden;
    float C2 = (xs[0] * e1y - ys[0] * e1x) * rden;

    float iz0 = 1.0f / zs[0], iz1 = 1.0f / zs[1], iz2 = 1.0f / zs[2];
    float d1 = iz1 - iz0, d2 = iz2 - iz0;
    float Az = A1 * d1 + A2 * d2;
    float Bz = B1 * d1 + B2 * d2;
    float Cz = iz0 + C1 * d1 + C2 * d2;

    if (!(valid && front)) C1 = __int_as_float(0x7FC00000);  // NaN

    g_fa[idx] = make_float4(A1, B1, C1, A2);
    g_fb[idx] = make_float4(B2, C2, Az, Bz);
    g_fc[idx] = make_float4(Cz, iz0, iz1, iz2);
    g_cz[idx] = Cz;
}

// block (8,16,4) = 512 threads = 16 warps; tile = 16x16 px;
// each thread: 2 adjacent x-pixels, 1 of 4 face slices.
__global__ void __launch_bounds__(512, 3)
raster_kernel(const float* __restrict__ image_ref,
              float* __restrict__ out,
              int B, int F, int S) {
    __shared__ int    slist[FCAP];
    __shared__ float4 sa[FCAP];
    __shared__ float4 sb[FCAP];
    __shared__ float  sc[FCAP];
    __shared__ int    swcnt[16];
    __shared__ float  swred[16];
    __shared__ float  smiv[3 * 256];   // slices 1..3, per pixel (pair*2+sub)
    __shared__ int    smfc[3 * 256];
    __shared__ int    slast;

    const int b     = blockIdx.z;
    const int slice = threadIdx.z;                      // 0..3
    const int pix   = threadIdx.y * 8 + threadIdx.x;    // 0..127 (pixel pair)
    const int tid   = slice * 128 + pix;
    const int warp  = tid >> 5;
    const int lane  = tid & 31;
    const int x0    = blockIdx.x * 16 + threadIdx.x * 2;
    const int y     = blockIdx.y * 16 + threadIdx.y;
    const float invS = 1.0f / (float)S;
    const float step = 2.0f * invS;
    const float py  = (2.0f * (float)y  + 1.0f - (float)S) * invS;
    const float pxA = (2.0f * (float)x0 + 1.0f - (float)S) * invS;
    const float pxB = pxA + step;
    const bool activeA = (x0 < S) && (y < S);
    const bool activeB = (x0 + 1 < S) && (y < S);

    // tile rect (pixel centers): center + half extents in NDC
    const float cxc = (2.0f * ((float)(blockIdx.x * 16) + 7.5f) + 1.0f - (float)S) * invS;
    const float cyc = (2.0f * ((float)(blockIdx.y * 16) + 7.5f) + 1.0f - (float)S) * invS;
    const float hw  = 15.0f * invS;
    const float hh  = 15.0f * invS;

    const float4* fa_g = g_fa + (size_t)b * F;
    const float4* fb_g = g_fb + (size_t)b * F;
    const float4* fc_g = g_fc + (size_t)b * F;
    const float*  cz_g = g_cz + (size_t)b * F;

    // fused exact-halfplane cull + ordered compaction + staging (512 wide)
    int cnt = 0;
    for (int base = 0; base < F; base += 512) {
        int f = base + tid;
        bool ok = false;
        float4 fa, fb;
        if (f < F) {
            fa = fa_g[f];
            fb = fb_g[f];
            float w1c = fmaf(fa.x, cxc, fmaf(fa.y, cyc, fa.z));
            float w2c = fmaf(fa.w, cxc, fmaf(fb.x, cyc, fb.y));
            float r1  = fmaf(fabsf(fa.x), hw, fabsf(fa.y) * hh);
            float r2  = fmaf(fabsf(fa.w), hw, fabsf(fb.x) * hh);
            float a0  = fa.x + fa.w, b0 = fa.y + fb.x;
            float w0c = 1.0f - w1c - w2c;
            float r0  = fmaf(fabsf(a0), hw, fabsf(b0) * hh);
            ok = (w1c + r1 >= 0.0f) && (w2c + r2 >= 0.0f) && (w0c + r0 >= 0.0f);
        }
        unsigned m = __ballot_sync(0xffffffffu, ok);
        int lanePfx = __popc(m & ((1u << lane) - 1u));
        if (lane == 0) swcnt[warp] = __popc(m);
        __syncthreads();
        int wbase = cnt;
#pragma unroll
        for (int w = 0; w < 16; w++) {
            int c = swcnt[w];
            if (w < warp) wbase += c;
            cnt += c;
        }
        if (ok) {
            int pos = wbase + lanePfx;
            slist[pos] = f;
            sa[pos] = fa;
            sb[pos] = fb;
            sc[pos] = cz_g[f];
        }
        __syncthreads();
    }
    const int nf = cnt;

    // each slice scans faces i ≡ slice (mod 4); 2 pixels per thread
    float bivA = EPSF, bivB = EPSF;
    int   biA = -1,   biB = -1;
#pragma unroll 4
    for (int i = slice; i < nf; i += 4) {
        const float4 fa = sa[i];
        const float4 fb = sb[i];
        const float  cz = sc[i];
        float t1 = fmaf(fa.y, py, fa.z);
        float t2 = fmaf(fb.x, py, fb.y);
        float tz = fmaf(fb.w, py, cz);
        float w1A = fmaf(fa.x, pxA, t1), w1B = fmaf(fa.x, pxB, t1);
        float w2A = fmaf(fa.w, pxA, t2), w2B = fmaf(fa.w, pxB, t2);
        float ivA = fmaf(fb.z, pxA, tz), ivB = fmaf(fb.z, pxB, tz);
        float sA = w1A + w2A, sB = w1B + w2B;
        if (w1A >= 0.0f && w2A >= 0.0f && sA <= 1.0f && ivA > bivA) {
            bivA = ivA; biA = i;
        }
        if (w1B >= 0.0f && w2B >= 0.0f && sB <= 1.0f && ivB > bivB) {
            bivB = ivB; biB = i;
        }
    }
    int bfA = (biA >= 0) ? slist[biA] : -1;
    int bfB = (biB >= 0) ? slist[biB] : -1;

    // deterministic 4-way merge: max invz, ties -> smaller face id
    if (slice > 0) {
        int o = (slice - 1) * 256 + pix * 2;
        smiv[o]     = bivA; smfc[o]     = bfA;
        smiv[o + 1] = bivB; smfc[o + 1] = bfB;
    }
    __syncthreads();
    if (slice == 0) {
#pragma unroll
        for (int s = 0; s < 3; s++) {
            int o = s * 256 + pix * 2;
            float ivc = smiv[o];     int fc0 = smfc[o];
            if (fc0 >= 0 && (bfA < 0 || ivc > bivA ||
                             (ivc == bivA && fc0 < bfA))) { bivA = ivc; bfA = fc0; }
            float ivd = smiv[o + 1]; int fc1 = smfc[o + 1];
            if (fc1 >= 0 && (bfB < 0 || ivd > bivB ||
                             (ivd == bivB && fc1 < bfB))) { bivB = ivd; bfB = fc1; }
        }
    }

    // epilogue on slice 0: perspective-correct trilinear texture + sq error
    float lsum = 0.0f;
    if (slice == 0) {
#pragma unroll
        for (int sub = 0; sub < 2; sub++) {
            const bool act = sub ? activeB : activeA;
            if (!act) continue;
            const float px = sub ? pxB : pxA;
            const int   f  = sub ? bfB : bfA;
            const int   xx = x0 + sub;
            float c0 = 0.0f, c1 = 0.0f, c2 = 0.0f;
            if (f >= 0) {
                const float4 fa = fa_g[f];
                const float4 fb = fb_g[f];
                const float4 fc = fc_g[f];
                float w1 = fmaf(fa.x, px, fmaf(fa.y, py, fa.z));
                float w2 = fmaf(fa.w, px, fmaf(fb.x, py, fb.y));
                float iv = fmaf(fb.z, px, fmaf(fb.w, py, fc.x));
                float w0 = 1.0f - w1 - w2;
                float iz = fmaxf(iv, EPSF);
                float r  = 1.0f / iz;
                float wp0 = __saturatef(w0 * fc.y * r);
                float wp1 = __saturatef(w1 * fc.z * r);
                float wp2 = __saturatef(w2 * fc.w * r);
                float q0 = 1.0f - wp0, q1 = 1.0f - wp1, q2 = 1.0f - wp2;
                float wA = q0 * q1, wB = q0 * wp1, wC = wp0 * q1, wD = wp0 * wp1;
                float w000 = wA * q2, w001 = wA * wp2;
                float w010 = wB * q2, w011 = wB * wp2;
                float w100 = wC * q2, w101 = wC * wp2;
                float w110 = wD * q2, w111 = wD * wp2;

                float tv[24];
#pragma unroll
                for (int q = 0; q < 6; q++) {
                    float4 v = g_tex4[f * 6 + q];
                    tv[q * 4 + 0] = v.x; tv[q * 4 + 1] = v.y;
                    tv[q * 4 + 2] = v.z; tv[q * 4 + 3] = v.w;
                }
#pragma unroll
                for (int c = 0; c < 3; c++) {
                    float col = w000 * tv[0 + c]  + w001 * tv[3 + c]
                              + w010 * tv[6 + c]  + w011 * tv[9 + c]
                              + w100 * tv[12 + c] + w101 * tv[15 + c]
                              + w110 * tv[18 + c] + w111 * tv[21 + c];
                    if (c == 0) c0 = col; else if (c == 1) c1 = col; else c2 = col;
                }
            }
            float rv0 = image_ref[((size_t)(b * 3 + 0) * S + y) * S + xx];
            float rv1 = image_ref[((size_t)(b * 3 + 1) * S + y) * S + xx];
            float rv2 = image_ref[((size_t)(b * 3 + 2) * S + y) * S + xx];
            float d0 = c0 - rv0, d1 = c1 - rv1, d2 = c2 - rv2;
            lsum += d0 * d0 + d1 * d1 + d2 * d2;
        }
    }

    // deterministic block reduction (16 warps; slices 1-3 contribute 0)
#pragma unroll
    for (int o = 16; o > 0; o >>= 1)
        lsum += __shfl_down_sync(0xffffffffu, lsum, o);
    if (lane == 0) swred[warp] = lsum;
    __syncthreads();

    const int nb = gridDim.x * gridDim.y * gridDim.z;
    const int bid = blockIdx.z * gridDim.x * gridDim.y
                  + blockIdx.y * gridDim.x + blockIdx.x;
    if (tid == 0) {
        float s = 0.0f;
#pragma unroll
        for (int w = 0; w < 16; w++) s += swred[w];
        g_part[bid] = s;
        __threadfence();
        int t = atomicAdd(&g_cnt, 1);
        slast = (t == nb - 1);
    }
    __syncthreads();

    // last block: deterministic fixed-order final reduction
    if (slast) {
        float s = 0.0f;
        for (int i = tid; i < nb; i += 512) s += g_part[i];
#pragma unroll
        for (int o = 16; o > 0; o >>= 1)
            s += __shfl_down_sync(0xffffffffu, s, o);
        if (lane == 0) swred[warp] = s;
        __syncthreads();
        if (tid == 0) {
            float tot = 0.0f;
#pragma unroll
            for (int w = 0; w < 16; w++) tot += swred[w];
            out[0] = tot;
            g_cnt = 0;   // reset for next graph replay
        }
    }
}

extern "C" void kernel_launch(void* const* d_in, const int* in_sizes, int n_in,
                              void* d_out, int out_size) {
    const float* vertices  = (const float*)d_in[0];
    const int*   faces     = (const int*)  d_in[1];
    const float* Kmat      = (const float*)d_in[2];
    const float* Rmat      = (const float*)d_in[3];
    const float* tvec      = (const float*)d_in[4];
    const float* textures  = (const float*)d_in[5];
    const float* image_ref = (const float*)d_in[6];

    int B = in_sizes[2] / 9;
    int V = in_sizes[0] / (3 * B);
    int F = in_sizes[1] / (3 * B);
    int ss = in_sizes[6] / (3 * B);
    int S = (int)(sqrt((double)ss) + 0.5);

    float* out = (float*)d_out;

    int prepN = (B * F > F * 24) ? B * F : F * 24;
    prep_kernel<<<(prepN + 255) / 256, 256>>>(vertices, faces, Kmat, Rmat,
                                              tvec, textures, B, V, F, S);

    dim3 blk(8, 16, 4);
    dim3 grd((S + 15) / 16, (S + 15) / 16, B);
    raster_kernel<<<grd, blk>>>(image_ref, out, B, F, S);
}